// round 10
// baseline (speedup 1.0000x reference)
#include <cuda_runtime.h>
#include <cstdint>

// Fixed shapes
#define BB   4
#define NN   4096
#define CC   128
#define DD   132      // 3 point dims + 128 feature dims + 1 zero pad
#define NPT  1024
#define NBLK 32       // blocks per batch
#define PPB  128      // points per block
#define THR  128      // threads per block (1 thread = 1 point)

// Statics (~8.5 MB)
__device__ float g_F[BB][NN][DD];                  // features, point-major (fp32)
__device__ float g_aa[BB][NN];                     // fp32 norms, Grace-NEON reduce order
__device__ volatile float g_rval[BB][2][NBLK];     // reduction slots (parity buffered)
__device__ volatile int   g_ridx[BB][2][NBLK];
__device__ volatile int   g_rtag[BB][2][NBLK];

// ---------------------------------------------------------------------------
// Prep: point-major rows + aa with XLA:CPU-on-Grace semantics:
// LLVM loop-vectorized reduce, VF=4 (NEON) x IC=2: 8 strided fma lanes over
// k=0..127, lanewise v0+v1, ARM faddp horizontal ((x0+x1)+(x2+x3)),
// then scalar-fma tail for k=128..130.
// ---------------------------------------------------------------------------
__global__ void prep_kernel(const float* __restrict__ pts,
                            const float* __restrict__ feat)
{
    int t = blockIdx.x * blockDim.x + threadIdx.x;
    if (t >= BB * NN) return;
    int b = t / NN;
    int n = t % NN;

    float* grow = &g_F[b][n][0];
    float row[DD];

    row[0] = pts[((size_t)b * NN + n) * 3 + 0];
    row[1] = pts[((size_t)b * NN + n) * 3 + 1];
    row[2] = pts[((size_t)b * NN + n) * 3 + 2];

    const float* fb = feat + (size_t)b * CC * NN + n;
    #pragma unroll 4
    for (int c = 0; c < CC; c++) row[3 + c] = fb[(size_t)c * NN];
    row[131] = 0.0f;

    // Vector body: 16 iterations x 8 lanes (two 4-lane NEON accumulators).
    float v0[4] = {0.f, 0.f, 0.f, 0.f};
    float v1[4] = {0.f, 0.f, 0.f, 0.f};
    #pragma unroll
    for (int i = 0; i < 16; i++) {
        #pragma unroll
        for (int j = 0; j < 4; j++) {
            float x0 = row[8 * i + j];
            v0[j] = __fmaf_rn(x0, x0, v0[j]);
            float x1 = row[8 * i + 4 + j];
            v1[j] = __fmaf_rn(x1, x1, v1[j]);
        }
    }
    // Combine interleaved accumulators lanewise, then faddp pairwise reduce.
    float l0 = __fadd_rn(v0[0], v1[0]);
    float l1 = __fadd_rn(v0[1], v1[1]);
    float l2 = __fadd_rn(v0[2], v1[2]);
    float l3 = __fadd_rn(v0[3], v1[3]);
    float h  = __fadd_rn(__fadd_rn(l0, l1), __fadd_rn(l2, l3));
    // Scalar epilogue: k = 128..130.
    h = __fmaf_rn(row[128], row[128], h);
    h = __fmaf_rn(row[129], row[129], h);
    h = __fmaf_rn(row[130], row[130], h);

    g_aa[b][n] = h;

    #pragma unroll 4
    for (int k = 0; k < DD; k++) grow[k] = row[k];
}

// ---------------------------------------------------------------------------
// Persistent FPS: 128 blocks, features in registers.
// dot = Eigen-style single-accumulator sequential fp32 FMA, k ascending.
// d = fadd(fadd(aa_i, aa_j), -fmul(2, ab)); fp32 mind; first-occurrence argmax.
// ---------------------------------------------------------------------------
__global__ void __launch_bounds__(THR) fps_kernel(const float* __restrict__ pts,
                                                  const float* __restrict__ feat,
                                                  float* __restrict__ out)
{
    const int blk  = blockIdx.x;
    const int b    = blk >> 5;
    const int bk   = blk & 31;
    const int t    = threadIdx.x;
    const int lane = t & 31;
    const int w    = t >> 5;
    const int n    = bk * PPB + t;    // global point id owned by this thread

    // Reset both parity tags of my slot before any use this launch.
    if (t == 0) { g_rtag[b][0][bk] = 0; g_rtag[b][1][bk] = 0; }
    __threadfence();

    // My point's feature vector in registers (coalesced loads).
    float fr[DD];
    {
        const float* pb = pts + ((size_t)b * NN + n) * 3;
        fr[0] = pb[0]; fr[1] = pb[1]; fr[2] = pb[2];
        const float* fb = feat + (size_t)b * CC * NN + n;
        #pragma unroll
        for (int c = 0; c < CC; c++) fr[3 + c] = fb[(size_t)c * NN];
        fr[131] = 0.0f;
    }

    __shared__ __align__(16) float s_fl[DD];
    __shared__ float  s_aal;
    __shared__ float  s_wv[4];
    __shared__ int    s_wi[4];
    __shared__ int    s_cur;

    const float aa_i = g_aa[b][n];

    float mind = 1e10f;
    int cur = 0;

    for (int s = 0; s < NPT; s++) {
        const int p = s & 1;
        if (bk == 0 && t == 0) out[b * NPT + s] = (float)cur;

        // Broadcast f_cur + aa_cur
        if (t < 33) ((float4*)s_fl)[t] = ((const float4*)&g_F[b][cur][0])[t];
        if (t == 33) s_aal = g_aa[b][cur];
        __syncthreads();

        // Sequential single-accumulator fp32 FMA dot, k ascending (Eigen order).
        float ab = 0.0f;
        #pragma unroll
        for (int k = 0; k < 131; k++)
            ab = __fmaf_rn(fr[k], s_fl[k], ab);

        // Reference rounding: t1 = fadd(aa_i, aa_j); d = t1 - 2*ab (2*ab exact).
        float d = __fadd_rn(__fadd_rn(aa_i, s_aal), -__fmul_rn(2.0f, ab));
        mind = fminf(mind, d);

        // Block argmax (first occurrence on ties -> smaller index)
        float v = mind; int idx = n;
        #pragma unroll
        for (int off = 16; off; off >>= 1) {
            float v2 = __shfl_down_sync(0xffffffffu, v, off);
            int   i2 = __shfl_down_sync(0xffffffffu, idx, off);
            if (v2 > v || (v2 == v && i2 < idx)) { v = v2; idx = i2; }
        }
        if (lane == 0) { s_wv[w] = v; s_wi[w] = idx; }
        __syncthreads();

        if (t == 0) {
            for (int u = 1; u < 4; u++) {
                if (s_wv[u] > v || (s_wv[u] == v && s_wi[u] < idx)) {
                    v = s_wv[u]; idx = s_wi[u];
                }
            }
            g_rval[b][p][bk] = v;
            g_ridx[b][p][bk] = idx;
            __threadfence();                 // release payload before tag
            g_rtag[b][p][bk] = s + 1;
        }

        // Warp 0 polls all 32 slots, reduces, broadcasts.
        if (w == 0) {
            while (g_rtag[b][p][lane] != s + 1) { }
            __threadfence();                 // acquire before payload read
            float pv = g_rval[b][p][lane];
            int   pi = g_ridx[b][p][lane];
            #pragma unroll
            for (int off = 16; off; off >>= 1) {
                float v2 = __shfl_down_sync(0xffffffffu, pv, off);
                int   i2 = __shfl_down_sync(0xffffffffu, pi, off);
                if (v2 > pv || (v2 == pv && i2 < pi)) { pv = v2; pi = i2; }
            }
            if (lane == 0) s_cur = pi;
        }
        __syncthreads();
        cur = s_cur;
    }
}

// ---------------------------------------------------------------------------
extern "C" void kernel_launch(void* const* d_in, const int* in_sizes, int n_in,
                              void* d_out, int out_size)
{
    const float* points   = nullptr;
    const float* features = nullptr;
    for (int i = 0; i < n_in; i++) {
        long long sz = in_sizes[i];
        if (sz == (long long)BB * NN * 3)       points   = (const float*)d_in[i];
        else if (sz == (long long)BB * CC * NN) features = (const float*)d_in[i];
    }
    if (!points)   points   = (const float*)d_in[0];
    if (!features) features = (const float*)d_in[1];

    float* out = (float*)d_out;
    (void)out_size;

    prep_kernel<<<(BB * NN + 255) / 256, 256>>>(points, features);
    fps_kernel<<<BB * NBLK, THR>>>(points, features, out);
}

// round 11
// speedup vs baseline: 1.4327x; 1.4327x over previous
#include <cuda_runtime.h>
#include <cstdint>

// Fixed shapes
#define BB   4
#define NN   4096
#define CC   128
#define DD   132      // 3 point dims + 128 feature dims + 1 zero pad
#define NPT  1024

// Cluster config (fast path)
#define CPB  16       // CTAs per batch = cluster size (non-portable)
#define THR  256      // threads per CTA, 1 point per thread

// Fallback config (proven round-10 path)
#define FB_NBLK 32
#define FB_THR  128

// Statics
__device__ float g_aa[BB][NN];                         // fp32 norms, Grace-NEON order
__device__ volatile float g_rval[BB][2][FB_NBLK];      // fallback sync slots
__device__ volatile int   g_ridx[BB][2][FB_NBLK];
__device__ volatile int   g_rtag[BB][2][FB_NBLK];

// ---------------------------------------------------------------------------
// mbarrier / cluster PTX helpers
// ---------------------------------------------------------------------------
__device__ __forceinline__ uint32_t smem_u32(const void* p) {
    uint32_t a;
    asm("{ .reg .u64 t; cvta.to.shared.u64 t, %1; cvt.u32.u64 %0, t; }"
        : "=r"(a) : "l"(p));
    return a;
}
__device__ __forceinline__ void mbar_init(uint32_t a, uint32_t cnt) {
    asm volatile("mbarrier.init.shared.b64 [%0], %1;" :: "r"(a), "r"(cnt) : "memory");
}
__device__ __forceinline__ uint32_t mapa_u32(uint32_t a, uint32_t rank) {
    uint32_t r;
    asm("mapa.shared::cluster.u32 %0, %1, %2;" : "=r"(r) : "r"(a), "r"(rank));
    return r;
}
__device__ __forceinline__ void st_cluster_u64(uint32_t a, unsigned long long v) {
    asm volatile("st.shared::cluster.u64 [%0], %1;" :: "r"(a), "l"(v) : "memory");
}
__device__ __forceinline__ void st_cluster_u32(uint32_t a, uint32_t v) {
    asm volatile("st.shared::cluster.u32 [%0], %1;" :: "r"(a), "r"(v) : "memory");
}
__device__ __forceinline__ void mbar_arrive_local(uint32_t a) {
    asm volatile("mbarrier.arrive.release.cta.shared::cta.b64 _, [%0];" :: "r"(a) : "memory");
}
__device__ __forceinline__ void mbar_arrive_cluster(uint32_t a) {
    asm volatile("mbarrier.arrive.release.cluster.shared::cluster.b64 _, [%0];" :: "r"(a) : "memory");
}
__device__ __forceinline__ void mbar_wait_par_acq_cluster(uint32_t a, uint32_t parity) {
    uint32_t done;
    do {
        asm volatile(
            "{\n\t.reg .pred p;\n\t"
            "mbarrier.try_wait.parity.acquire.cluster.shared::cta.b64 p, [%1], %2, 0x989680;\n\t"
            "selp.b32 %0, 1, 0, p;\n\t}"
            : "=r"(done) : "r"(a), "r"(parity) : "memory");
    } while (!done);
}
__device__ __forceinline__ void cluster_sync_all() {
    asm volatile("barrier.cluster.arrive.aligned;" ::: "memory");
    asm volatile("barrier.cluster.wait.aligned;" ::: "memory");
}

// ---------------------------------------------------------------------------
// Prep: aa only (exact Grace/LLVM NEON reduce order, identical to round 10).
// ---------------------------------------------------------------------------
__global__ void prep_kernel(const float* __restrict__ pts,
                            const float* __restrict__ feat)
{
    int t = blockIdx.x * blockDim.x + threadIdx.x;
    if (t >= BB * NN) return;
    int b = t / NN;
    int n = t % NN;

    const float* fb = feat + (size_t)b * CC * NN + n;

    float v0[4] = {0.f, 0.f, 0.f, 0.f};
    float v1[4] = {0.f, 0.f, 0.f, 0.f};

    // k = 0..2 : point dims
    {
        const float* pb = pts + ((size_t)b * NN + n) * 3;
        float p0 = pb[0], p1 = pb[1], p2 = pb[2];
        v0[0] = __fmaf_rn(p0, p0, v0[0]);
        v0[1] = __fmaf_rn(p1, p1, v0[1]);
        v0[2] = __fmaf_rn(p2, p2, v0[2]);
    }
    // k = 3..127 : features c = 0..124, lane = acc[((k>>2)&1)][k&3]
    #pragma unroll 5
    for (int c = 0; c < 125; c++) {
        int k = 3 + c;
        float x = fb[(size_t)c * NN];
        if (((k >> 2) & 1) == 0) v0[k & 3] = __fmaf_rn(x, x, v0[k & 3]);
        else                     v1[k & 3] = __fmaf_rn(x, x, v1[k & 3]);
    }
    // lanewise combine + faddp pairwise horizontal
    float l0 = __fadd_rn(v0[0], v1[0]);
    float l1 = __fadd_rn(v0[1], v1[1]);
    float l2 = __fadd_rn(v0[2], v1[2]);
    float l3 = __fadd_rn(v0[3], v1[3]);
    float h  = __fadd_rn(__fadd_rn(l0, l1), __fadd_rn(l2, l3));
    // scalar tail: c = 125..127
    float x5 = fb[(size_t)125 * NN];  h = __fmaf_rn(x5, x5, h);
    float x6 = fb[(size_t)126 * NN];  h = __fmaf_rn(x6, x6, h);
    float x7 = fb[(size_t)127 * NN];  h = __fmaf_rn(x7, x7, h);

    g_aa[b][n] = h;
}

// ---------------------------------------------------------------------------
// FAST PATH: one 16-CTA cluster per batch, DSMEM mbarrier sync.
// Numerics identical to the passing round-10 kernel.
// ---------------------------------------------------------------------------
__global__ void __launch_bounds__(THR, 1) __cluster_dims__(CPB, 1, 1)
fps_cluster_kernel(const float* __restrict__ pts,
                   const float* __restrict__ feat,
                   float* __restrict__ out)
{
    const int blk  = blockIdx.x;
    const int b    = blk / CPB;
    const int rank = blk % CPB;
    const int t    = threadIdx.x;
    const int lane = t & 31;
    const int w    = t >> 5;
    const int n    = rank * THR + t;     // global point id

    __shared__ __align__(8) unsigned long long s_gbar;         // gather bar (count 16)
    __shared__ __align__(8) unsigned long long s_rbar;         // result bar (count 1)
    __shared__ __align__(8) unsigned long long s_slots[2][CPB];
    __shared__ float s_fl[DD];
    __shared__ float s_aal;
    __shared__ float s_wv[THR / 32];
    __shared__ int   s_wi[THR / 32];
    __shared__ int   s_cur;

    const uint32_t gbar_a = smem_u32((const void*)&s_gbar);
    const uint32_t rbar_a = smem_u32((const void*)&s_rbar);
    const uint32_t cur_a  = smem_u32((const void*)&s_cur);

    if (t == 0) {
        mbar_init(gbar_a, CPB);
        mbar_init(rbar_a, 1);
    }
    __syncthreads();
    cluster_sync_all();     // all bars initialized before any remote arrive

    // My point's features in registers (identical bits to prior rounds).
    float fr[DD];
    {
        const float* pb = pts + ((size_t)b * NN + n) * 3;
        fr[0] = pb[0]; fr[1] = pb[1]; fr[2] = pb[2];
        const float* fb = feat + (size_t)b * CC * NN + n;
        #pragma unroll
        for (int c = 0; c < CC; c++) fr[3 + c] = fb[(size_t)c * NN];
        fr[131] = 0.0f;
    }
    const float aa_i = g_aa[b][n];

    float mind = 1e10f;
    int cur = 0;

    for (int s = 0; s < NPT; s++) {
        const int p = s & 1;
        if (rank == 0 && t == 0) out[b * NPT + s] = (float)cur;

        // Broadcast f_cur + aa_cur directly from inputs (same bits as g_F did).
        if (t < 3)        s_fl[t] = pts[((size_t)b * NN + cur) * 3 + t];
        else if (t < 131) s_fl[t] = feat[(size_t)b * CC * NN + (size_t)(t - 3) * NN + cur];
        else if (t == 131) s_aal = g_aa[b][cur];
        __syncthreads();

        // Sequential single-accumulator fp32 FMA dot (frozen numerics).
        float ab = 0.0f;
        #pragma unroll
        for (int k = 0; k < 131; k++)
            ab = __fmaf_rn(fr[k], s_fl[k], ab);
        float d = __fadd_rn(__fadd_rn(aa_i, s_aal), -__fmul_rn(2.0f, ab));
        mind = fminf(mind, d);

        // Intra-CTA argmax (ties -> smaller index).
        float v = mind; int idx = n;
        #pragma unroll
        for (int off = 16; off; off >>= 1) {
            float v2 = __shfl_down_sync(0xffffffffu, v, off);
            int   i2 = __shfl_down_sync(0xffffffffu, idx, off);
            if (v2 > v || (v2 == v && i2 < idx)) { v = v2; idx = i2; }
        }
        if (lane == 0) { s_wv[w] = v; s_wi[w] = idx; }
        __syncthreads();

        if (t == 0) {
            v = s_wv[0]; idx = s_wi[0];
            #pragma unroll
            for (int u = 1; u < THR / 32; u++)
                if (s_wv[u] > v || (s_wv[u] == v && s_wi[u] < idx)) { v = s_wv[u]; idx = s_wi[u]; }

            unsigned long long pack =
                ((unsigned long long)__float_as_uint(v) << 32) | (unsigned)idx;
            if (rank == 0) {
                s_slots[p][0] = pack;
                mbar_arrive_local(gbar_a);
            } else {
                st_cluster_u64(mapa_u32(smem_u32((const void*)&s_slots[p][rank]), 0), pack);
                mbar_arrive_cluster(mapa_u32(gbar_a, 0));
            }
        }

        // CTA0 warp0: gather, reduce 16 slots, multicast result.
        if (rank == 0 && w == 0) {
            mbar_wait_par_acq_cluster(gbar_a, p);
            float pv = -3.402823466e38f;
            int   pi = 0x7fffffff;
            if (lane < CPB) {
                unsigned long long pk = s_slots[p][lane];
                pv = __uint_as_float((unsigned)(pk >> 32));
                pi = (int)(unsigned)(pk & 0xffffffffULL);
            }
            #pragma unroll
            for (int off = 16; off; off >>= 1) {
                float v2 = __shfl_down_sync(0xffffffffu, pv, off);
                int   i2 = __shfl_down_sync(0xffffffffu, pi, off);
                if (v2 > pv || (v2 == pv && i2 < pi)) { pv = v2; pi = i2; }
            }
            int c0 = __shfl_sync(0xffffffffu, pi, 0);
            if (lane < CPB) {
                if (lane == 0) {
                    s_cur = c0;
                    mbar_arrive_local(rbar_a);
                } else {
                    st_cluster_u32(mapa_u32(cur_a, lane), (uint32_t)c0);
                    mbar_arrive_cluster(mapa_u32(rbar_a, lane));
                }
            }
        }

        mbar_wait_par_acq_cluster(rbar_a, p);
        cur = s_cur;
    }

    cluster_sync_all();     // no CTA exits while remote ops may target it
}

// ---------------------------------------------------------------------------
// FALLBACK: round-10 global-sync kernel (proven), with direct f_cur loads.
// ---------------------------------------------------------------------------
__global__ void __launch_bounds__(FB_THR) fps_fallback_kernel(
    const float* __restrict__ pts,
    const float* __restrict__ feat,
    float* __restrict__ out)
{
    const int blk  = blockIdx.x;
    const int b    = blk >> 5;
    const int bk   = blk & 31;
    const int t    = threadIdx.x;
    const int lane = t & 31;
    const int w    = t >> 5;
    const int n    = bk * FB_THR + t;

    if (t == 0) { g_rtag[b][0][bk] = 0; g_rtag[b][1][bk] = 0; }
    __threadfence();

    float fr[DD];
    {
        const float* pb = pts + ((size_t)b * NN + n) * 3;
        fr[0] = pb[0]; fr[1] = pb[1]; fr[2] = pb[2];
        const float* fb = feat + (size_t)b * CC * NN + n;
        #pragma unroll
        for (int c = 0; c < CC; c++) fr[3 + c] = fb[(size_t)c * NN];
        fr[131] = 0.0f;
    }

    __shared__ float s_fl[DD];
    __shared__ float s_aal;
    __shared__ float s_wv[4];
    __shared__ int   s_wi[4];
    __shared__ int   s_cur;

    const float aa_i = g_aa[b][n];

    float mind = 1e10f;
    int cur = 0;

    for (int s = 0; s < NPT; s++) {
        const int p = s & 1;
        if (bk == 0 && t == 0) out[b * NPT + s] = (float)cur;

        if (t < 3) {
            s_fl[t] = pts[((size_t)b * NN + cur) * 3 + t];
            s_fl[128 + t] = feat[(size_t)b * CC * NN + (size_t)(125 + t) * NN + cur];
        } else {
            s_fl[t] = feat[(size_t)b * CC * NN + (size_t)(t - 3) * NN + cur];
            if (t == 3) s_aal = g_aa[b][cur];
        }
        __syncthreads();

        float ab = 0.0f;
        #pragma unroll
        for (int k = 0; k < 131; k++)
            ab = __fmaf_rn(fr[k], s_fl[k], ab);
        float d = __fadd_rn(__fadd_rn(aa_i, s_aal), -__fmul_rn(2.0f, ab));
        mind = fminf(mind, d);

        float v = mind; int idx = n;
        #pragma unroll
        for (int off = 16; off; off >>= 1) {
            float v2 = __shfl_down_sync(0xffffffffu, v, off);
            int   i2 = __shfl_down_sync(0xffffffffu, idx, off);
            if (v2 > v || (v2 == v && i2 < idx)) { v = v2; idx = i2; }
        }
        if (lane == 0) { s_wv[w] = v; s_wi[w] = idx; }
        __syncthreads();

        if (t == 0) {
            for (int u = 1; u < 4; u++)
                if (s_wv[u] > v || (s_wv[u] == v && s_wi[u] < idx)) { v = s_wv[u]; idx = s_wi[u]; }
            g_rval[b][p][bk] = v;
            g_ridx[b][p][bk] = idx;
            __threadfence();
            g_rtag[b][p][bk] = s + 1;
        }

        if (w == 0) {
            while (g_rtag[b][p][lane] != s + 1) { }
            __threadfence();
            float pv = g_rval[b][p][lane];
            int   pi = g_ridx[b][p][lane];
            #pragma unroll
            for (int off = 16; off; off >>= 1) {
                float v2 = __shfl_down_sync(0xffffffffu, pv, off);
                int   i2 = __shfl_down_sync(0xffffffffu, pi, off);
                if (v2 > pv || (v2 == pv && i2 < pi)) { pv = v2; pi = i2; }
            }
            if (lane == 0) s_cur = pi;
        }
        __syncthreads();
        cur = s_cur;
    }
}

// ---------------------------------------------------------------------------
extern "C" void kernel_launch(void* const* d_in, const int* in_sizes, int n_in,
                              void* d_out, int out_size)
{
    const float* points   = nullptr;
    const float* features = nullptr;
    for (int i = 0; i < n_in; i++) {
        long long sz = in_sizes[i];
        if (sz == (long long)BB * NN * 3)       points   = (const float*)d_in[i];
        else if (sz == (long long)BB * CC * NN) features = (const float*)d_in[i];
    }
    if (!points)   points   = (const float*)d_in[0];
    if (!features) features = (const float*)d_in[1];

    float* out = (float*)d_out;
    (void)out_size;

    prep_kernel<<<(BB * NN + 255) / 256, 256>>>(points, features);

    // Deterministic capability check for the 16-CTA (non-portable) cluster path.
    bool cluster_ok = false;
    {
        cudaError_t e = cudaFuncSetAttribute(
            (const void*)fps_cluster_kernel,
            cudaFuncAttributeNonPortableClusterSizeAllowed, 1);
        if (e == cudaSuccess) {
            cudaLaunchConfig_t cfg = {};
            cfg.gridDim  = dim3(BB * CPB, 1, 1);
            cfg.blockDim = dim3(THR, 1, 1);
            cudaLaunchAttribute attrs[1];
            attrs[0].id = cudaLaunchAttributeClusterDimension;
            attrs[0].val.clusterDim = {CPB, 1, 1};
            cfg.attrs = attrs;
            cfg.numAttrs = 1;
            int num = 0;
            cudaError_t e2 = cudaOccupancyMaxActiveClusters(
                &num, (const void*)fps_cluster_kernel, &cfg);
            cluster_ok = (e2 == cudaSuccess && num >= 1);
        }
        (void)cudaGetLastError();   // clear any non-sticky error state
    }

    if (cluster_ok) {
        fps_cluster_kernel<<<BB * CPB, THR>>>(points, features, out);
    } else {
        fps_fallback_kernel<<<BB * FB_NBLK, FB_THR>>>(points, features, out);
    }
}